// round 15
// baseline (speedup 1.0000x reference)
#include <cuda_runtime.h>

// out[b,u] = prod_f(in[b,f]*w[f,u]) + bias[u] = P[b]*W[u] + bias[u]
// B=32768, F=32, U=256.
static constexpr int Bn = 32768;
static constexpr int Fn = 32;
static constexpr int Un = 256;

static constexpr int THREADS       = 256;               // 8 warps
static constexpr int ROWS_PER_WARP = 8;                 // 2 independent LDG.128/lane
static constexpr int ROWS_PER_BLK  = ROWS_PER_WARP * 8; // 64
static constexpr int GRID          = Bn / ROWS_PER_BLK; // 512 -> one wave

// Packed fp32x2 helpers (sm_103a FFMA2 is PTX-only).
__device__ __forceinline__ unsigned long long pk2(float lo, float hi) {
    unsigned long long r;
    asm("mov.b64 %0, {%1, %2};" : "=l"(r) : "f"(lo), "f"(hi));
    return r;
}
__device__ __forceinline__ unsigned long long fma2(unsigned long long a,
                                                   unsigned long long b,
                                                   unsigned long long c) {
    unsigned long long d;
    asm("fma.rn.f32x2 %0, %1, %2, %3;" : "=l"(d) : "l"(a), "l"(b), "l"(c));
    return d;
}
// 16B streaming store (evict-first): STG.E.128 with .cs cache op.
__device__ __forceinline__ void stcs2(ulonglong2* p, unsigned long long x,
                                      unsigned long long y) {
    asm volatile("st.global.cs.v2.u64 [%0], {%1, %2};"
                 :: "l"(p), "l"(x), "l"(y) : "memory");
}

// One wave, everything resident, MLP=2 input loads, streaming stores.
__global__ __launch_bounds__(THREADS)
void fused_kernel(const float* __restrict__ in,
                  const float* __restrict__ w,
                  const float* __restrict__ bias,
                  float* __restrict__ out) {
    __shared__ float sW[Un];

    const int t    = threadIdx.x;
    const int lane = t & 31;
    const int warp = t >> 5;

    // ---- issue BOTH input loads first: 8 rows * 32 f = 64 float4 ----
    const long long rowbase = (long long)blockIdx.x * ROWS_PER_BLK
                            + (long long)warp * ROWS_PER_WARP;
    const float4* in4 = reinterpret_cast<const float4*>(in + rowbase * Fn);
    const float4 v0 = in4[lane];          // rows rowbase..+3, lane l -> row l>>3
    const float4 v1 = in4[lane + 32];     // rows rowbase+4..+7

    // ---- one-time W phase: thread t owns column t (R13-proven scalar form) ----
    {
        float q0 = 1.0f, q1 = 1.0f, q2 = 1.0f, q3 = 1.0f;
#pragma unroll
        for (int f = 0; f < Fn; f += 4) {
            q0 *= w[(f + 0) * Un + t];
            q1 *= w[(f + 1) * Un + t];
            q2 *= w[(f + 2) * Un + t];
            q3 *= w[(f + 3) * Un + t];
        }
        sW[t] = (q0 * q1) * (q2 * q3);
    }

    // bias -> regs, independent of everything above
    const float4* B4 = reinterpret_cast<const float4*>(bias);
    const float4 bv0 = B4[lane];
    const float4 bv1 = B4[lane + 32];

    __syncthreads();

    const float4* sW4 = reinterpret_cast<const float4*>(sW);
    const float4 wv0 = sW4[lane];
    const float4 wv1 = sW4[lane + 32];

    const unsigned long long w00 = pk2(wv0.x, wv0.y), w01 = pk2(wv0.z, wv0.w);
    const unsigned long long w10 = pk2(wv1.x, wv1.y), w11 = pk2(wv1.z, wv1.w);
    const unsigned long long b00 = pk2(bv0.x, bv0.y), b01 = pk2(bv0.z, bv0.w);
    const unsigned long long b10 = pk2(bv1.x, bv1.y), b11 = pk2(bv1.z, bv1.w);

    // ---- two interleaved row-product reductions (independent chains) ----
    float p0 = v0.x * v0.y * v0.z * v0.w;
    float p1 = v1.x * v1.y * v1.z * v1.w;
    p0 *= __shfl_xor_sync(0xffffffffu, p0, 1);
    p1 *= __shfl_xor_sync(0xffffffffu, p1, 1);
    p0 *= __shfl_xor_sync(0xffffffffu, p0, 2);
    p1 *= __shfl_xor_sync(0xffffffffu, p1, 2);
    p0 *= __shfl_xor_sync(0xffffffffu, p0, 4);
    p1 *= __shfl_xor_sync(0xffffffffu, p1, 4);
    // lanes 8r..8r+7: p0 = product of row (rowbase+r), p1 = row (rowbase+4+r)

    // ---- 16 coalesced streaming STG.128 per warp, all independent ----
    ulonglong2* out2 = reinterpret_cast<ulonglong2*>(out + rowbase * Un);
#pragma unroll
    for (int r = 0; r < 4; ++r) {
        const float pr0 = __shfl_sync(0xffffffffu, p0, r * 8);
        const float pr1 = __shfl_sync(0xffffffffu, p1, r * 8);
        const unsigned long long pa = pk2(pr0, pr0);
        const unsigned long long pb = pk2(pr1, pr1);
        // row stride = 256 floats = 64 ulonglong2
        stcs2(&out2[(r    ) * 64 + lane],
              fma2(pa, w00, b00), fma2(pa, w01, b01));
        stcs2(&out2[(r    ) * 64 + lane + 32],
              fma2(pa, w10, b10), fma2(pa, w11, b11));
        stcs2(&out2[(r + 4) * 64 + lane],
              fma2(pb, w00, b00), fma2(pb, w01, b01));
        stcs2(&out2[(r + 4) * 64 + lane + 32],
              fma2(pb, w10, b10), fma2(pb, w11, b11));
    }
}

extern "C" void kernel_launch(void* const* d_in, const int* in_sizes, int n_in,
                              void* d_out, int out_size) {
    // metadata order: inputs [B,F], weight [F,U], weight_selector [F,U] (dead), bias [U]
    const float* in   = (const float*)d_in[0];
    const float* w    = (const float*)d_in[1];
    const float* bias = (const float*)d_in[3];
    float* out        = (float*)d_out;

    fused_kernel<<<GRID, THREADS>>>(in, w, bias, out);
}